// round 6
// baseline (speedup 1.0000x reference)
#include <cuda_runtime.h>
#include <math.h>

// MatchLoss: per src point (16384x3 f32) find 2nd-nearest tgt (16384x3),
// pd = ||src - tgt[idx2]||, mv = (pd<1e-3)+1e-7, out = log(1+sum(exp(mv))).
//
// key = 0.5*|t|^2 - s.t is monotone in ||s-t|| per src: 3 FFMA/pair.
// Top-2 tracked branchlessly by VALUE only (3 FMNMX/pair); 2nd-NN distance
// recovered as d^2 = 2*key2 + |s|^2 (no index tracking).
#define NPTS           16384
#define NSPLIT         16         // warps per block, each scans 1/16 of tgt tile
#define TILE           2048       // tgt points staged in SMEM per tile
#define SRC_PER_THREAD 2
#define SRC_PER_BLOCK  (32 * SRC_PER_THREAD)  // 64
#define NBLOCKS        (NPTS / SRC_PER_BLOCK) // 256
#define THREADS        (32 * NSPLIT)          // 512

#define RADIUS_F  1e-3f
#define EPS_F     1e-7f
#define BIG       3.402823466e+38f

__device__ float g_partials[NBLOCKS];
__device__ int   g_count = 0;   // self-restoring: last block resets to 0

__global__ __launch_bounds__(THREADS, 3)
void ml_nn2_kernel(const float* __restrict__ src, const float* __restrict__ tgt,
                   float* __restrict__ out) {
    // 32 KB tile; after the main loop the same storage is reused for the
    // per-warp partial top-2 keys (2 * 16 * 64 * 4B = 8 KB), keeping static
    // SMEM at ~32 KB so 3 blocks co-reside per SM.
    __shared__ float4 tile[TILE];
    __shared__ float  swsum[NSPLIT];
    float* const sb1 = reinterpret_cast<float*>(tile);                        // [NSPLIT][SRC_PER_BLOCK]
    float* const sb2 = reinterpret_cast<float*>(tile) + NSPLIT * SRC_PER_BLOCK;

    const int tid  = threadIdx.x;
    const int warp = tid >> 5;
    const int lane = tid & 31;

    // Each thread owns SRC_PER_THREAD src points: base + lane + 32*r.
    // Store NEGATED coords so key = fma(t, -s, ...) chains cleanly.
    const int sbase = blockIdx.x * SRC_PER_BLOCK + lane;
    float nsx[SRC_PER_THREAD], nsy[SRC_PER_THREAD], nsz[SRC_PER_THREAD];
    float b1[SRC_PER_THREAD], b2[SRC_PER_THREAD];
    #pragma unroll
    for (int r = 0; r < SRC_PER_THREAD; ++r) {
        const int s = sbase + 32 * r;
        nsx[r] = -src[3 * s + 0];
        nsy[r] = -src[3 * s + 1];
        nsz[r] = -src[3 * s + 2];
        b1[r] = BIG; b2[r] = BIG;
    }

    const int chunk = TILE / NSPLIT;   // 128 tgt points per warp per tile
    const int wbase = warp * chunk;

    for (int tb = 0; tb < NPTS; tb += TILE) {
        // Cooperative tile load (tgt is L2-resident): w slot = 0.5*|t|^2
        for (int k = tid; k < TILE; k += THREADS) {
            const int p = 3 * (tb + k);
            const float tx = tgt[p], ty = tgt[p + 1], tz = tgt[p + 2];
            const float tw = 0.5f * fmaf(tx, tx, fmaf(ty, ty, tz * tz));
            tile[k] = make_float4(tx, ty, tz, tw);
        }
        __syncthreads();

        #pragma unroll 16
        for (int k = 0; k < chunk; ++k) {
            const float4 t = tile[wbase + k];        // warp-uniform LDS.128 broadcast
            #pragma unroll
            for (int r = 0; r < SRC_PER_THREAD; ++r) {
                // key = 0.5*|t|^2 - s.t : monotone in ||s-t|| for fixed s
                const float key = fmaf(t.x, nsx[r], fmaf(t.y, nsy[r], fmaf(t.z, nsz[r], t.w)));
                // exact branchless top-2 (3x FMNMX, alu pipe)
                b2[r] = fminf(b2[r], fmaxf(b1[r], key));
                b1[r] = fminf(b1[r], key);
            }
        }
        __syncthreads();
    }

    // Publish per-split partial top-2 keys into the (now dead) tile storage
    #pragma unroll
    for (int r = 0; r < SRC_PER_THREAD; ++r) {
        sb1[warp * SRC_PER_BLOCK + lane + 32 * r] = b1[r];
        sb2[warp * SRC_PER_BLOCK + lane + 32 * r] = b2[r];
    }
    __syncthreads();

    // Threads 0..SRC_PER_BLOCK-1: merge 16 partials for one src point each,
    // recover d^2 of the 2nd-NN, accumulate exp(match_val).
    float contrib = 0.0f;
    if (tid < SRC_PER_BLOCK) {
        float m1 = BIG, m2 = BIG;
        #pragma unroll
        for (int w = 0; w < NSPLIT; ++w) {
            float d = sb1[w * SRC_PER_BLOCK + tid];
            m2 = fminf(m2, fmaxf(m1, d));
            m1 = fminf(m1, d);
            d = sb2[w * SRC_PER_BLOCK + tid];
            m2 = fminf(m2, fmaxf(m1, d));
            m1 = fminf(m1, d);
        }
        const int s = blockIdx.x * SRC_PER_BLOCK + tid;
        const float px = src[3 * s + 0], py = src[3 * s + 1], pz = src[3 * s + 2];
        const float s2 = fmaf(px, px, fmaf(py, py, pz * pz));
        const float d2 = fmaxf(fmaf(2.0f, m2, s2), 0.0f);  // ||s - t_2nd||^2
        const float pd = sqrtf(d2);
        const float mv = (pd < RADIUS_F ? 1.0f : 0.0f) + EPS_F;
        contrib = expf(mv);
    }

    // Block-level reduction of the SRC_PER_BLOCK contributions
    if (tid < SRC_PER_BLOCK) {
        #pragma unroll
        for (int o = 16; o > 0; o >>= 1)
            contrib += __shfl_down_sync(0xFFFFFFFFu, contrib, o);
        if (lane == 0) swsum[warp] = contrib;
    }
    __syncthreads();

    if (tid == 0) {
        float bs = 0.0f;
        #pragma unroll
        for (int w = 0; w < SRC_PER_BLOCK / 32; ++w) bs += swsum[w];
        g_partials[blockIdx.x] = bs;
        __threadfence();
        const int done = atomicAdd(&g_count, 1);
        swsum[0] = (done == NBLOCKS - 1) ? 1.0f : 0.0f;   // am I last?
    }
    __syncthreads();

    // Last block: reduce all partials, write output, restore counter.
    if (swsum[0] != 0.0f) {
        float v = (tid < NBLOCKS) ? g_partials[tid] : 0.0f;
        #pragma unroll
        for (int o = 16; o > 0; o >>= 1)
            v += __shfl_down_sync(0xFFFFFFFFu, v, o);
        __shared__ float fin[THREADS / 32];
        if (lane == 0) fin[warp] = v;
        __syncthreads();
        if (tid == 0) {
            float s = 0.0f;
            #pragma unroll
            for (int w = 0; w < (NBLOCKS + 31) / 32 && w < THREADS / 32; ++w) s += fin[w];
            out[0] = logf(1.0f + s);   // softplus(logsumexp(mv))
            g_count = 0;               // restore for next graph replay
        }
    }
}

extern "C" void kernel_launch(void* const* d_in, const int* in_sizes, int n_in,
                              void* d_out, int out_size) {
    const float* src = (const float*)d_in[0];  // src_coords [16384, 3]
    const float* tgt = (const float*)d_in[1];  // tgt_coords [16384, 3]
    float* out = (float*)d_out;
    ml_nn2_kernel<<<NBLOCKS, THREADS>>>(src, tgt, out);
}

// round 7
// speedup vs baseline: 2.4882x; 2.4882x over previous
#include <cuda_runtime.h>
#include <math.h>

// MatchLoss: per src point (16384x3 f32), is the 2nd-nearest tgt within 1e-3?
// mv = (pd<1e-3)+1e-7 with pd = ||src - tgt_2nd + 1e-6||; out = log(1+sum(exp(mv))).
// Since mv takes only two values, out = log(1 + (N-m)*e^eps + m*e^(1+eps)) where
// m = #src with pd<1e-3. Fixed-radius search via spatial hash (cell = 1.1e-3):
// any tgt with d < 1.05e-3 is inside the 27-cell neighborhood; exact pd is
// recomputed from the candidate 2nd-NN coordinates. Missed points have
// d >= 1.1e-3 and cannot change the decision.
#define NPTS      16384
#define HBITS     16
#define HSIZE     (1 << HBITS)
#define QBLOCKS   (NPTS / 256)

#define EPS_F     1e-7f
#define CELL_F    1.1e-3f
#define INV_CELL  (1.0f / CELL_F)
#define R2CUT     (1.05e-3f * 1.05e-3f)   // gate for candidate 2nd-NN
#define RAD2      (1e-3f * 1e-3f)         // pd^2 threshold
#define BIG       3.402823466e+38f

__device__ int       g_head[HSIZE];
__device__ int       g_next[NPTS];
__device__ long long g_ckey[NPTS];
__device__ int       g_match;
__device__ int       g_done = 0;   // self-restoring completion counter

__device__ __forceinline__ unsigned int cell_hash(int cx, int cy, int cz) {
    unsigned int h = (unsigned int)(cx * 73856093) ^
                     (unsigned int)(cy * 19349663) ^
                     (unsigned int)(cz * 83492791);
    return h & (HSIZE - 1);
}

__device__ __forceinline__ long long cell_key(int cx, int cy, int cz) {
    return (((long long)(cx + (1 << 20))) << 42) |
           (((long long)(cy + (1 << 20))) << 21) |
            ((long long)(cz + (1 << 20)));
}

__global__ void ml_clear_kernel() {
    const int i = blockIdx.x * blockDim.x + threadIdx.x;
    if (i < HSIZE) g_head[i] = -1;
    if (i == 0) g_match = 0;
}

__global__ void ml_build_kernel(const float* __restrict__ tgt) {
    const int i = blockIdx.x * blockDim.x + threadIdx.x;
    if (i >= NPTS) return;
    const float x = tgt[3 * i + 0], y = tgt[3 * i + 1], z = tgt[3 * i + 2];
    const int cx = (int)floorf(x * INV_CELL);
    const int cy = (int)floorf(y * INV_CELL);
    const int cz = (int)floorf(z * INV_CELL);
    g_ckey[i] = cell_key(cx, cy, cz);
    const unsigned int h = cell_hash(cx, cy, cz);
    g_next[i] = atomicExch(&g_head[h], i);
}

__global__ __launch_bounds__(256)
void ml_query_kernel(const float* __restrict__ src, const float* __restrict__ tgt,
                     float* __restrict__ out) {
    __shared__ int swarp[8];
    const int tid  = threadIdx.x;
    const int lane = tid & 31;
    const int warp = tid >> 5;
    const int i = blockIdx.x * 256 + tid;

    const float px = src[3 * i + 0], py = src[3 * i + 1], pz = src[3 * i + 2];
    const int cx = (int)floorf(px * INV_CELL);
    const int cy = (int)floorf(py * INV_CELL);
    const int cz = (int)floorf(pz * INV_CELL);

    float d1 = BIG, d2 = BIG;          // top-2 squared distances
    float q1x = 0, q1y = 0, q1z = 0;   // best coords
    float q2x = 0, q2y = 0, q2z = 0;   // 2nd-best coords

    #pragma unroll
    for (int dx = -1; dx <= 1; ++dx)
    #pragma unroll
    for (int dy = -1; dy <= 1; ++dy)
    #pragma unroll
    for (int dz = -1; dz <= 1; ++dz) {
        const int ccx = cx + dx, ccy = cy + dy, ccz = cz + dz;
        const long long pkey = cell_key(ccx, ccy, ccz);
        for (int e = g_head[cell_hash(ccx, ccy, ccz)]; e >= 0; e = g_next[e]) {
            if (g_ckey[e] != pkey) continue;   // collision or other probe's cell
            const float tx = tgt[3 * e + 0], ty = tgt[3 * e + 1], tz = tgt[3 * e + 2];
            const float ex = px - tx, ey = py - ty, ez = pz - tz;
            const float dd = fmaf(ex, ex, fmaf(ey, ey, ez * ez));
            if (dd < d2) {
                if (dd < d1) {
                    d2 = d1; q2x = q1x; q2y = q1y; q2z = q1z;
                    d1 = dd; q1x = tx;  q1y = ty;  q1z = tz;
                } else {
                    d2 = dd; q2x = tx;  q2y = ty;  q2z = tz;
                }
            }
        }
    }

    int m = 0;
    if (d2 <= R2CUT) {
        // exact reference pd: componentwise +1e-6 before the norm
        const float ex = px - q2x + 1e-6f;
        const float ey = py - q2y + 1e-6f;
        const float ez = pz - q2z + 1e-6f;
        const float pd2 = fmaf(ex, ex, fmaf(ey, ey, ez * ez));
        if (pd2 < RAD2) m = 1;
    }

    // Block reduce match count (integer: deterministic)
    #pragma unroll
    for (int o = 16; o > 0; o >>= 1)
        m += __shfl_down_sync(0xFFFFFFFFu, m, o);
    if (lane == 0) swarp[warp] = m;
    __syncthreads();
    if (tid == 0) {
        int bs = 0;
        #pragma unroll
        for (int w = 0; w < 8; ++w) bs += swarp[w];
        if (bs) atomicAdd(&g_match, bs);
        __threadfence();
        const int done = atomicAdd(&g_done, 1);
        if (done == QBLOCKS - 1) {
            const int mm = g_match;
            const float S = (float)(NPTS - mm) * expf(EPS_F)
                          + (float)mm * expf(1.0f + EPS_F);
            out[0] = logf(1.0f + S);   // softplus(logsumexp(mv))
            g_done = 0;                // restore for next graph replay
        }
    }
}

extern "C" void kernel_launch(void* const* d_in, const int* in_sizes, int n_in,
                              void* d_out, int out_size) {
    const float* src = (const float*)d_in[0];  // src_coords [16384, 3]
    const float* tgt = (const float*)d_in[1];  // tgt_coords [16384, 3]
    float* out = (float*)d_out;

    ml_clear_kernel<<<HSIZE / 256, 256>>>();
    ml_build_kernel<<<NPTS / 256, 256>>>(tgt);
    ml_query_kernel<<<QBLOCKS, 256>>>(src, tgt, out);
}